// round 3
// baseline (speedup 1.0000x reference)
#include <cuda_runtime.h>
#include <cstdint>
#include <cstddef>

// Problem: StackedHighwayBiLSTM  L=3, H=512, DIN=512, T=256, B=64
// out = [256,64,1024] (16777216) ++ h_n [6,64,512] (196608) ++ c_n [6,64,512]

#define M_TOT 16384              // T*B rows
#define NG    4096               // 2 dirs * 4 gates * 512

// -------- scratch (static device globals; allocation-free) --------
__device__ float g_gates[(size_t)M_TOT * NG];     // 256 MB gate pre-activations
__device__ float g_bufA[(size_t)M_TOT * 1024];    // layer I/O ping (64 MB)
__device__ float g_bufB[(size_t)M_TOT * 1024];    // layer I/O pong (64 MB)
__device__ float g_h[2 * 2 * 64 * 512];           // [dir][parity][b][k] h state
__device__ unsigned g_cnt;
__device__ volatile unsigned g_gen;

__device__ __forceinline__ float sigm(float x) { return 1.f / (1.f + __expf(-x)); }

// Grid-wide barrier. All 128 CTAs are co-resident (grid <= #SMs, 1 CTA/SM fits).
__device__ __forceinline__ void gridbar(unsigned nb) {
    __threadfence();
    __syncthreads();
    if (threadIdx.x == 0) {
        unsigned g = g_gen;
        if (atomicAdd(&g_cnt, 1u) == nb - 1u) {
            atomicExch(&g_cnt, 0u);
            __threadfence();
            g_gen = g + 1u;
        } else {
            while (g_gen == g) { __nanosleep(32); }
            __threadfence();
        }
    }
    __syncthreads();
}

// ---------------------------------------------------------------------------
// GEMM: C[M,N] = A[M,K] @ Wrow[N,K]^T (+bias).  Rows n<nsplit come from W0,
// else from W1 (two weight blocks, fwd/bwd).  128x128x16 tiles, 256 thr, 8x8.
// MODE 0: C = acc + bias
// MODE 1: g = sigmoid(acc+bias); C = g*raw + (1-g)*inp    (highway epilogue)
// ---------------------------------------------------------------------------
template <int MODE>
__global__ __launch_bounds__(256, 2)
void gemm_k(const float* __restrict__ A, int M, int K, int N,
            const float* __restrict__ W0, const float* __restrict__ W1, int nsplit,
            const float* __restrict__ b0, const float* __restrict__ b1,
            float* __restrict__ C,
            const float* __restrict__ raw, const float* __restrict__ inp)
{
    __shared__ __align__(16) float As[16][132];
    __shared__ __align__(16) float Bs[16][132];
    const int tid = threadIdx.x;
    const int m0 = blockIdx.y * 128;
    const int n0 = blockIdx.x * 128;
    const float* W   = (n0 < nsplit) ? (W0 + (size_t)n0 * K) : (W1 + (size_t)(n0 - nsplit) * K);
    const float* bia = (n0 < nsplit) ? (b0 + n0) : (b1 + (n0 - nsplit));
    const int lrow = tid >> 2;
    const int lk   = (tid & 3) * 4;
    const int tm   = tid >> 4;
    const int tn   = tid & 15;

    float acc[8][8];
#pragma unroll
    for (int i = 0; i < 8; i++)
#pragma unroll
        for (int j = 0; j < 8; j++) acc[i][j] = 0.f;

    for (int kc = 0; kc < K; kc += 16) {
        float4 a0 = *(const float4*)(A + (size_t)(m0 + lrow) * K + kc + lk);
        float4 a1 = *(const float4*)(A + (size_t)(m0 + lrow + 64) * K + kc + lk);
        float4 w0 = *(const float4*)(W + (size_t)lrow * K + kc + lk);
        float4 w1 = *(const float4*)(W + (size_t)(lrow + 64) * K + kc + lk);
        __syncthreads();
        As[lk + 0][lrow] = a0.x; As[lk + 1][lrow] = a0.y;
        As[lk + 2][lrow] = a0.z; As[lk + 3][lrow] = a0.w;
        As[lk + 0][lrow + 64] = a1.x; As[lk + 1][lrow + 64] = a1.y;
        As[lk + 2][lrow + 64] = a1.z; As[lk + 3][lrow + 64] = a1.w;
        Bs[lk + 0][lrow] = w0.x; Bs[lk + 1][lrow] = w0.y;
        Bs[lk + 2][lrow] = w0.z; Bs[lk + 3][lrow] = w0.w;
        Bs[lk + 0][lrow + 64] = w1.x; Bs[lk + 1][lrow + 64] = w1.y;
        Bs[lk + 2][lrow + 64] = w1.z; Bs[lk + 3][lrow + 64] = w1.w;
        __syncthreads();
#pragma unroll
        for (int k = 0; k < 16; k++) {
            float ra[8], rb[8];
            *(float4*)&ra[0] = *(const float4*)&As[k][tm * 8];
            *(float4*)&ra[4] = *(const float4*)&As[k][tm * 8 + 4];
            *(float4*)&rb[0] = *(const float4*)&Bs[k][tn * 8];
            *(float4*)&rb[4] = *(const float4*)&Bs[k][tn * 8 + 4];
#pragma unroll
            for (int i = 0; i < 8; i++)
#pragma unroll
                for (int j = 0; j < 8; j++) acc[i][j] += ra[i] * rb[j];
        }
    }

#pragma unroll
    for (int i = 0; i < 8; i++) {
        size_t m = (size_t)(m0 + tm * 8 + i);
        float* crow = C + m * N + n0 + tn * 8;
#pragma unroll
        for (int jj = 0; jj < 8; jj += 4) {
            float4 v;
            if (MODE == 0) {
                v.x = acc[i][jj + 0] + bia[tn * 8 + jj + 0];
                v.y = acc[i][jj + 1] + bia[tn * 8 + jj + 1];
                v.z = acc[i][jj + 2] + bia[tn * 8 + jj + 2];
                v.w = acc[i][jj + 3] + bia[tn * 8 + jj + 3];
            } else {
                const float* rrow = raw + m * N + n0 + tn * 8;
                const float* prow = inp + m * N + n0 + tn * 8;
                float4 rv = *(const float4*)(rrow + jj);
                float4 pv = *(const float4*)(prow + jj);
                float gx;
                gx = sigm(acc[i][jj + 0] + bia[tn * 8 + jj + 0]); v.x = gx * rv.x + (1.f - gx) * pv.x;
                gx = sigm(acc[i][jj + 1] + bia[tn * 8 + jj + 1]); v.y = gx * rv.y + (1.f - gx) * pv.y;
                gx = sigm(acc[i][jj + 2] + bia[tn * 8 + jj + 2]); v.z = gx * rv.z + (1.f - gx) * pv.z;
                gx = sigm(acc[i][jj + 3] + bia[tn * 8 + jj + 3]); v.w = gx * rv.w + (1.f - gx) * pv.w;
            }
            *(float4*)(crow + jj) = v;
        }
    }
}

// ---------------------------------------------------------------------------
// Persistent bidirectional LSTM recurrence for one layer.
// 128 CTAs x 256 thr. CTA c: dir = c>>6, hidden-unit block u0 = (c&63)*8.
// Each CTA computes, per step, hW for its 8 units x 4 gates x 64 batches
// (K=512 split over warp pairs), reduces in smem, then does the elementwise
// LSTM update with c-state resident in smem.  h state double-buffered in L2.
// ---------------------------------------------------------------------------
__global__ __launch_bounds__(256, 1)
void recur_k(const float* __restrict__ Wf, const float* __restrict__ Wb,    // [2048,512]
             const float* __restrict__ initf, const float* __restrict__ initb, // [2,512]
             const float* __restrict__ masks,  // [T*B]
             const float* __restrict__ gates,  // [16384,4096]
             float* __restrict__ rawout,       // [16384,1024]
             float* __restrict__ hn, float* __restrict__ cn) // each [2][64][512]
{
    __shared__ __align__(16) float part[4 * 32 * 64]; // [ksl][col][b] 32 KB
    __shared__ float csh[512];                        // c-state [b][u]

    const int tid = threadIdx.x;
    const int cta = blockIdx.x;
    const int dir = cta >> 6;
    const int u0  = (cta & 63) * 8;
    const float* W    = dir ? Wb : Wf;
    const float* init = dir ? initb : initf;

    const int w    = tid >> 5;
    const int lane = tid & 31;
    const int ksl  = w >> 1;              // 0..3  K slice of 128
    const int ch   = w & 1;               // col half
    const int cb   = lane >> 4;           // col sub-block
    const int bb4  = (lane & 15) * 4;     // batch base (4 batches)
    const int c0   = ch * 16 + cb * 8;    // local col base = gi*8
    const int gi   = c0 >> 3;             // gate index 0..3
    const int k0   = ksl * 128;

    // init h0 (buffer parity 0) and c0
    for (int cid = tid; cid < 512; cid += 256) {
        int b = cid >> 3, j = cid & 7;
        csh[cid] = init[512 + u0 + j];
        g_h[(dir * 2 + 0) * 32768 + b * 512 + u0 + j] = init[u0 + j];
    }
    gridbar(128);

    const float* wb = W + (size_t)(gi * 512 + u0) * 512 + k0;

    for (int t = 0; t < 256; t++) {
        const int tt = dir ? (255 - t) : t;
        const int p  = t & 1;
        const float* hrd = g_h + (size_t)(dir * 2 + p) * 32768;

        // prefetch gate-x + mask for this thread's two LSTM cells (hides DRAM lat)
        float gxp[2][4], mv[2];
#pragma unroll
        for (int rep = 0; rep < 2; rep++) {
            int cid = tid + rep * 256;
            int b = cid >> 3, j = cid & 7;
            mv[rep] = masks[tt * 64 + b];
            const float* gx = gates + (size_t)(tt * 64 + b) * 4096 + dir * 2048 + u0 + j;
#pragma unroll
            for (int g4 = 0; g4 < 4; g4++) gxp[rep][g4] = gx[g4 * 512];
        }

        // ---- partial hW: 4 batches x 8 cols x 128 K per thread ----
        float acc[4][8];
#pragma unroll
        for (int i = 0; i < 4; i++)
#pragma unroll
            for (int j = 0; j < 8; j++) acc[i][j] = 0.f;

        const float* hb = hrd + (size_t)bb4 * 512 + k0;
#pragma unroll 2
        for (int k4 = 0; k4 < 128; k4 += 4) {
            float4 h0 = *(const float4*)(hb + k4);
            float4 h1 = *(const float4*)(hb + 512 + k4);
            float4 h2 = *(const float4*)(hb + 1024 + k4);
            float4 h3 = *(const float4*)(hb + 1536 + k4);
#pragma unroll
            for (int j = 0; j < 8; j++) {
                float4 wv = __ldg((const float4*)(wb + (size_t)j * 512 + k4));
                acc[0][j] += h0.x * wv.x + h0.y * wv.y + h0.z * wv.z + h0.w * wv.w;
                acc[1][j] += h1.x * wv.x + h1.y * wv.y + h1.z * wv.z + h1.w * wv.w;
                acc[2][j] += h2.x * wv.x + h2.y * wv.y + h2.z * wv.z + h2.w * wv.w;
                acc[3][j] += h3.x * wv.x + h3.y * wv.y + h3.z * wv.z + h3.w * wv.w;
            }
        }
        {
            float* pc = part + (ksl * 32 + c0) * 64 + bb4;
#pragma unroll
            for (int j = 0; j < 8; j++)
                *(float4*)(pc + j * 64) = make_float4(acc[0][j], acc[1][j], acc[2][j], acc[3][j]);
        }
        __syncthreads();

        // ---- reduce + elementwise LSTM (2 cells per thread) ----
#pragma unroll
        for (int rep = 0; rep < 2; rep++) {
            int cid = tid + rep * 256;
            int b = cid >> 3, j = cid & 7;
            float gs[4];
#pragma unroll
            for (int g4 = 0; g4 < 4; g4++) {
                float s = gxp[rep][g4];
#pragma unroll
                for (int ks = 0; ks < 4; ks++)
                    s += part[(ks * 32 + g4 * 8 + j) * 64 + b];
                gs[g4] = s;
            }
            float m  = mv[rep];
            float ii = sigm(gs[0]);
            float ff = sigm(gs[1]);
            float gg = tanhf(gs[2]);
            float oo = sigm(gs[3]);
            float cp = csh[cid];
            float cnv = (ff * cp + ii * gg) * m;
            float hnv = oo * tanhf(cnv) * m;
            csh[cid] = cnv;
            g_h[(size_t)(dir * 2 + (p ^ 1)) * 32768 + b * 512 + u0 + j] = hnv;
            rawout[(size_t)(tt * 64 + b) * 1024 + dir * 512 + u0 + j] = hnv;
            if (t == 255) {
                hn[dir * 32768 + b * 512 + u0 + j] = hnv;
                cn[dir * 32768 + b * 512 + u0 + j] = cnv;
            }
        }
        gridbar(128);
    }
}

// ---------------------------------------------------------------------------
extern "C" void kernel_launch(void* const* d_in, const int* in_sizes, int n_in,
                              void* d_out, int out_size) {
    const float* x     = (const float*)d_in[0];
    const float* masks = (const float*)d_in[1];
    const float* fWih0 = (const float*)d_in[2];
    const float* fWihR = (const float*)d_in[3];
    const float* fWhh  = (const float*)d_in[4];
    const float* fbi   = (const float*)d_in[5];
    const float* bWih0 = (const float*)d_in[6];
    const float* bWihR = (const float*)d_in[7];
    const float* bWhh  = (const float*)d_in[8];
    const float* bbi   = (const float*)d_in[9];
    const float* finit = (const float*)d_in[10];
    const float* binit = (const float*)d_in[11];
    const float* projW = (const float*)d_in[12];
    const float* projb = (const float*)d_in[13];
    float* out = (float*)d_out;

    float *gates, *bufA, *bufB;
    cudaGetSymbolAddress((void**)&gates, g_gates);
    cudaGetSymbolAddress((void**)&bufA, g_bufA);
    cudaGetSymbolAddress((void**)&bufB, g_bufB);

    float* hnb = out + 16777216;   // h_n region [6,64,512]
    float* cnb = out + 16973824;   // c_n region [6,64,512]

    dim3 blk(256);
    dim3 gGate(32, 128);   // N=4096, M=16384
    dim3 gProj(8, 128);    // N=1024

    // ---- Layer 0 ----
    gemm_k<0><<<gGate, blk>>>(x, M_TOT, 512, 4096, fWih0, bWih0, 2048,
                              fbi, bbi, gates, nullptr, nullptr);
    recur_k<<<128, blk>>>(fWhh, bWhh, finit, binit, masks, gates, bufA, hnb, cnb);

    // ---- Layer 1 ----
    gemm_k<0><<<gGate, blk>>>(bufA, M_TOT, 1024, 4096, fWihR, bWihR, 2048,
                              fbi + 2048, bbi + 2048, gates, nullptr, nullptr);
    recur_k<<<128, blk>>>(fWhh + 1048576, bWhh + 1048576, finit + 1024, binit + 1024,
                          masks, gates, bufB, hnb + 65536, cnb + 65536);
    // highway 1: bufA = g*bufB + (1-g)*bufA
    gemm_k<1><<<gProj, blk>>>(bufB, M_TOT, 1024, 1024, projW, projW, 1024,
                              projb, projb, bufA, bufB, bufA);

    // ---- Layer 2 ----
    gemm_k<0><<<gGate, blk>>>(bufA, M_TOT, 1024, 4096, fWihR + 2097152, bWihR + 2097152, 2048,
                              fbi + 4096, bbi + 4096, gates, nullptr, nullptr);
    recur_k<<<128, blk>>>(fWhh + 2097152, bWhh + 2097152, finit + 2048, binit + 2048,
                          masks, gates, bufB, hnb + 131072, cnb + 131072);
    // highway 2: d_out = g*bufB + (1-g)*bufA
    gemm_k<1><<<gProj, blk>>>(bufB, M_TOT, 1024, 1024, projW + 1048576, projW + 1048576, 1024,
                              projb + 1024, projb + 1024, out, bufB, bufA);
}

// round 5
// speedup vs baseline: 1.2650x; 1.2650x over previous
#include <cuda_runtime.h>
#include <cstdint>
#include <cstddef>

// Problem: StackedHighwayBiLSTM  L=3, H=512, DIN=512, T=256, B=64
// out = [256,64,1024] (16777216) ++ h_n [6,64,512] (196608) ++ c_n [6,64,512]

#define M_TOT 16384              // T*B rows
#define NG    4096               // 2 dirs * 4 gates * 512

typedef unsigned long long u64;

// -------- scratch (static device globals; allocation-free) --------
__device__ float g_gates[(size_t)M_TOT * NG];     // 256 MB gate pre-activations
__device__ float g_bufA[(size_t)M_TOT * 1024];    // layer I/O ping (64 MB)
__device__ float g_bufB[(size_t)M_TOT * 1024];    // layer I/O pong (64 MB)
__device__ float g_h[2 * 2 * 64 * 512];           // [dir][parity][b][k] h state
__device__ unsigned g_cnt;
__device__ volatile unsigned g_gen;

__device__ __forceinline__ float sigm(float x) { return 1.f / (1.f + __expf(-x)); }

// round f32 -> tf32 (rna); destination must be a .b32 register per PTX ISA
__device__ __forceinline__ unsigned totf(float x) {
    unsigned r; asm("cvt.rna.tf32.f32 %0, %1;" : "=r"(r) : "f"(x)); return r;
}
// packed dual-FMA on f32x2 (PTX ISA 8.6, sm_100+)
__device__ __forceinline__ void ffma2(u64& d, u64 a, u64 b) {
    asm("fma.rn.f32x2 %0, %1, %2, %3;" : "=l"(d) : "l"(a), "l"(b), "l"(d));
}
__device__ __forceinline__ float2 unpk(u64 v) {
    float2 r; asm("mov.b64 {%0,%1}, %2;" : "=f"(r.x), "=f"(r.y) : "l"(v)); return r;
}

// Grid-wide barrier. All 128 CTAs are co-resident (grid <= #SMs, 1 CTA/SM fits).
__device__ __forceinline__ void gridbar(unsigned nb) {
    __threadfence();
    __syncthreads();
    if (threadIdx.x == 0) {
        unsigned g = g_gen;
        if (atomicAdd(&g_cnt, 1u) == nb - 1u) {
            atomicExch(&g_cnt, 0u);
            __threadfence();
            g_gen = g + 1u;
        } else {
            while (g_gen == g) { __nanosleep(32); }
            __threadfence();
        }
    }
    __syncthreads();
}

// ---------------------------------------------------------------------------
// Tensor-core tf32 GEMM: C[M,N] = A[M,K] @ Wrow[N,K]^T (+bias).
// Rows n<nsplit come from W0, else W1.  CTA tile 128x128, k-tile 32,
// 256 thr = 8 warps (2x4), warp tile 64x32, mma.sync.m16n8k8 tf32.
// MODE 0: C = acc + bias
// MODE 1: g = sigmoid(acc+bias); C = g*raw + (1-g)*inp    (highway epilogue)
// ---------------------------------------------------------------------------
template <int MODE>
__global__ __launch_bounds__(256, 2)
void gemm_t(const float* __restrict__ A, int M, int K, int N,
            const float* __restrict__ W0, const float* __restrict__ W1, int nsplit,
            const float* __restrict__ b0, const float* __restrict__ b1,
            float* __restrict__ C,
            const float* __restrict__ raw, const float* __restrict__ inp)
{
    __shared__ __align__(16) unsigned As[128 * 36];  // [m][k] row stride 36, tf32 bits
    __shared__ __align__(16) unsigned Bs[128 * 36];  // [n][k] row stride 36, tf32 bits

    const int tid  = threadIdx.x;
    const int m0   = blockIdx.y * 128;
    const int n0   = blockIdx.x * 128;
    const float* W   = (n0 < nsplit) ? (W0 + (size_t)n0 * K) : (W1 + (size_t)(n0 - nsplit) * K);
    const float* bia = (n0 < nsplit) ? (b0 + n0) : (b1 + (n0 - nsplit));

    const int wid  = tid >> 5;
    const int lane = tid & 31;
    const int g    = lane >> 2;      // groupID 0..7
    const int tg   = lane & 3;       // thread-in-group 0..3
    const int wm   = (wid >> 2) * 64;   // warp m offset (0,64)
    const int wn   = (wid & 3) * 32;    // warp n offset (0..96)

    const int lrow = tid >> 1;           // staging row 0..127
    const int lkh  = (tid & 1) * 16;     // staging k half

    float cc[4][4][4];
#pragma unroll
    for (int mi = 0; mi < 4; mi++)
#pragma unroll
        for (int ni = 0; ni < 4; ni++)
#pragma unroll
            for (int r = 0; r < 4; r++) cc[mi][ni][r] = 0.f;

    const float* Arow = A + (size_t)(m0 + lrow) * K + lkh;
    const float* Wrow = W + (size_t)lrow * K + lkh;

    for (int kc = 0; kc < K; kc += 32) {
        float4 av[4], wv[4];
#pragma unroll
        for (int i = 0; i < 4; i++) {
            av[i] = *(const float4*)(Arow + kc + i * 4);
            wv[i] = *(const float4*)(Wrow + kc + i * 4);
        }
        __syncthreads();
#pragma unroll
        for (int i = 0; i < 4; i++) {
            uint4 a, w;
            a.x = totf(av[i].x); a.y = totf(av[i].y); a.z = totf(av[i].z); a.w = totf(av[i].w);
            w.x = totf(wv[i].x); w.y = totf(wv[i].y); w.z = totf(wv[i].z); w.w = totf(wv[i].w);
            *(uint4*)(As + lrow * 36 + lkh + i * 4) = a;
            *(uint4*)(Bs + lrow * 36 + lkh + i * 4) = w;
        }
        __syncthreads();

#pragma unroll
        for (int kk = 0; kk < 4; kk++) {
            const int kb = kk * 8 + tg;
            unsigned a[4][4], b[4][2];
#pragma unroll
            for (int mi = 0; mi < 4; mi++) {
                int r = wm + mi * 16 + g;
                a[mi][0] = As[r * 36 + kb];
                a[mi][1] = As[(r + 8) * 36 + kb];
                a[mi][2] = As[r * 36 + kb + 4];
                a[mi][3] = As[(r + 8) * 36 + kb + 4];
            }
#pragma unroll
            for (int ni = 0; ni < 4; ni++) {
                int n = wn + ni * 8 + g;
                b[ni][0] = Bs[n * 36 + kb];
                b[ni][1] = Bs[n * 36 + kb + 4];
            }
#pragma unroll
            for (int mi = 0; mi < 4; mi++)
#pragma unroll
                for (int ni = 0; ni < 4; ni++) {
                    asm volatile(
                        "mma.sync.aligned.m16n8k8.row.col.f32.tf32.tf32.f32 "
                        "{%0,%1,%2,%3}, {%4,%5,%6,%7}, {%8,%9}, {%0,%1,%2,%3};\n"
                        : "+f"(cc[mi][ni][0]), "+f"(cc[mi][ni][1]),
                          "+f"(cc[mi][ni][2]), "+f"(cc[mi][ni][3])
                        : "r"(a[mi][0]), "r"(a[mi][1]), "r"(a[mi][2]), "r"(a[mi][3]),
                          "r"(b[ni][0]), "r"(b[ni][1]));
                }
        }
    }

    // epilogue: c0,c1 -> (row g, cols 2tg,2tg+1); c2,c3 -> (row g+8, same cols)
#pragma unroll
    for (int mi = 0; mi < 4; mi++) {
        int r0 = m0 + wm + mi * 16 + g;
#pragma unroll
        for (int ni = 0; ni < 4; ni++) {
            int cl = wn + ni * 8 + 2 * tg;     // local col 0..127
            size_t o0 = (size_t)r0 * N + n0 + cl;
            size_t o1 = (size_t)(r0 + 8) * N + n0 + cl;
            float bx = bia[cl], by = bia[cl + 1];
            if (MODE == 0) {
                float2 v0 = make_float2(cc[mi][ni][0] + bx, cc[mi][ni][1] + by);
                float2 v1 = make_float2(cc[mi][ni][2] + bx, cc[mi][ni][3] + by);
                *(float2*)(C + o0) = v0;
                *(float2*)(C + o1) = v1;
            } else {
                float2 rv0 = *(const float2*)(raw + o0);
                float2 rv1 = *(const float2*)(raw + o1);
                float2 pv0 = *(const float2*)(inp + o0);
                float2 pv1 = *(const float2*)(inp + o1);
                float gx;
                float2 v0, v1;
                gx = sigm(cc[mi][ni][0] + bx); v0.x = gx * rv0.x + (1.f - gx) * pv0.x;
                gx = sigm(cc[mi][ni][1] + by); v0.y = gx * rv0.y + (1.f - gx) * pv0.y;
                gx = sigm(cc[mi][ni][2] + bx); v1.x = gx * rv1.x + (1.f - gx) * pv1.x;
                gx = sigm(cc[mi][ni][3] + by); v1.y = gx * rv1.y + (1.f - gx) * pv1.y;
                *(float2*)(C + o0) = v0;
                *(float2*)(C + o1) = v1;
            }
        }
    }
}

// ---------------------------------------------------------------------------
// Persistent bidirectional LSTM recurrence for one layer.
// 128 CTAs x 256 thr. CTA c: dir = c>>6, hidden-unit block u0 = (c&63)*8.
// hW dot products use packed fma.rn.f32x2 along K (both operands come packed
// for free from float4 loads).  h state double-buffered in L2.
// ---------------------------------------------------------------------------
__global__ __launch_bounds__(256, 1)
void recur_k(const float* __restrict__ Wf, const float* __restrict__ Wb,    // [2048,512]
             const float* __restrict__ initf, const float* __restrict__ initb, // [2,512]
             const float* __restrict__ masks,  // [T*B]
             const float* __restrict__ gates,  // [16384,4096]
             float* __restrict__ rawout,       // [16384,1024]
             float* __restrict__ hn, float* __restrict__ cn) // each [2][64][512]
{
    __shared__ __align__(16) float part[4 * 32 * 64]; // [ksl][col][b] 32 KB
    __shared__ float csh[512];                        // c-state [b][u]

    const int tid = threadIdx.x;
    const int cta = blockIdx.x;
    const int dir = cta >> 6;
    const int u0  = (cta & 63) * 8;
    const float* W    = dir ? Wb : Wf;
    const float* init = dir ? initb : initf;

    const int w    = tid >> 5;
    const int lane = tid & 31;
    const int ksl  = w >> 1;              // 0..3  K slice of 128
    const int ch   = w & 1;               // col half
    const int cb   = lane >> 4;           // col sub-block
    const int bb4  = (lane & 15) * 4;     // batch base (4 batches)
    const int c0   = ch * 16 + cb * 8;    // local col base = gi*8
    const int gi   = c0 >> 3;             // gate index 0..3
    const int k0   = ksl * 128;

    // init h0 (buffer parity 0) and c0
    for (int cid = tid; cid < 512; cid += 256) {
        int b = cid >> 3, j = cid & 7;
        csh[cid] = init[512 + u0 + j];
        g_h[(dir * 2 + 0) * 32768 + b * 512 + u0 + j] = init[u0 + j];
    }
    gridbar(128);

    const float* wb = W + (size_t)(gi * 512 + u0) * 512 + k0;

    for (int t = 0; t < 256; t++) {
        const int tt = dir ? (255 - t) : t;
        const int p  = t & 1;
        const float* hrd = g_h + (size_t)(dir * 2 + p) * 32768;

        // prefetch gate-x + mask for this thread's two LSTM cells
        float gxp[2][4], mv[2];
#pragma unroll
        for (int rep = 0; rep < 2; rep++) {
            int cid = tid + rep * 256;
            int b = cid >> 3, j = cid & 7;
            mv[rep] = masks[tt * 64 + b];
            const float* gx = gates + (size_t)(tt * 64 + b) * 4096 + dir * 2048 + u0 + j;
#pragma unroll
            for (int g4 = 0; g4 < 4; g4++) gxp[rep][g4] = gx[g4 * 512];
        }

        // ---- partial hW: 4 batches x 8 cols x 128 K per thread (f32x2 packed) ----
        u64 acc2[4][8];
#pragma unroll
        for (int i = 0; i < 4; i++)
#pragma unroll
            for (int j = 0; j < 8; j++) acc2[i][j] = 0ull;

        const float* hb = hrd + (size_t)bb4 * 512 + k0;
#pragma unroll 2
        for (int k4 = 0; k4 < 128; k4 += 4) {
            ulonglong2 H0 = *(const ulonglong2*)(hb + k4);
            ulonglong2 H1 = *(const ulonglong2*)(hb + 512 + k4);
            ulonglong2 H2 = *(const ulonglong2*)(hb + 1024 + k4);
            ulonglong2 H3 = *(const ulonglong2*)(hb + 1536 + k4);
#pragma unroll
            for (int j = 0; j < 8; j++) {
                ulonglong2 Wv = *(const ulonglong2*)(wb + (size_t)j * 512 + k4);
                ffma2(acc2[0][j], H0.x, Wv.x); ffma2(acc2[0][j], H0.y, Wv.y);
                ffma2(acc2[1][j], H1.x, Wv.x); ffma2(acc2[1][j], H1.y, Wv.y);
                ffma2(acc2[2][j], H2.x, Wv.x); ffma2(acc2[2][j], H2.y, Wv.y);
                ffma2(acc2[3][j], H3.x, Wv.x); ffma2(acc2[3][j], H3.y, Wv.y);
            }
        }
        {
            float* pc = part + (ksl * 32 + c0) * 64 + bb4;
#pragma unroll
            for (int j = 0; j < 8; j++) {
                float2 s0 = unpk(acc2[0][j]);
                float2 s1 = unpk(acc2[1][j]);
                float2 s2 = unpk(acc2[2][j]);
                float2 s3 = unpk(acc2[3][j]);
                *(float4*)(pc + j * 64) =
                    make_float4(s0.x + s0.y, s1.x + s1.y, s2.x + s2.y, s3.x + s3.y);
            }
        }
        __syncthreads();

        // ---- reduce + elementwise LSTM (2 cells per thread) ----
#pragma unroll
        for (int rep = 0; rep < 2; rep++) {
            int cid = tid + rep * 256;
            int b = cid >> 3, j = cid & 7;
            float gs[4];
#pragma unroll
            for (int g4 = 0; g4 < 4; g4++) {
                float s = gxp[rep][g4];
#pragma unroll
                for (int ks = 0; ks < 4; ks++)
                    s += part[(ks * 32 + g4 * 8 + j) * 64 + b];
                gs[g4] = s;
            }
            float m  = mv[rep];
            float ii = sigm(gs[0]);
            float ff = sigm(gs[1]);
            float gg = tanhf(gs[2]);
            float oo = sigm(gs[3]);
            float cp = csh[cid];
            float cnv = (ff * cp + ii * gg) * m;
            float hnv = oo * tanhf(cnv) * m;
            csh[cid] = cnv;
            g_h[(size_t)(dir * 2 + (p ^ 1)) * 32768 + b * 512 + u0 + j] = hnv;
            rawout[(size_t)(tt * 64 + b) * 1024 + dir * 512 + u0 + j] = hnv;
            if (t == 255) {
                hn[dir * 32768 + b * 512 + u0 + j] = hnv;
                cn[dir * 32768 + b * 512 + u0 + j] = cnv;
            }
        }
        gridbar(128);
    }
}

// ---------------------------------------------------------------------------
extern "C" void kernel_launch(void* const* d_in, const int* in_sizes, int n_in,
                              void* d_out, int out_size) {
    const float* x     = (const float*)d_in[0];
    const float* masks = (const float*)d_in[1];
    const float* fWih0 = (const float*)d_in[2];
    const float* fWihR = (const float*)d_in[3];
    const float* fWhh  = (const float*)d_in[4];
    const float* fbi   = (const float*)d_in[5];
    const float* bWih0 = (const float*)d_in[6];
    const float* bWihR = (const float*)d_in[7];
    const float* bWhh  = (const float*)d_in[8];
    const float* bbi   = (const float*)d_in[9];
    const float* finit = (const float*)d_in[10];
    const float* binit = (const float*)d_in[11];
    const float* projW = (const float*)d_in[12];
    const float* projb = (const float*)d_in[13];
    float* out = (float*)d_out;

    float *gates, *bufA, *bufB;
    cudaGetSymbolAddress((void**)&gates, g_gates);
    cudaGetSymbolAddress((void**)&bufA, g_bufA);
    cudaGetSymbolAddress((void**)&bufB, g_bufB);

    float* hnb = out + 16777216;   // h_n region [6,64,512]
    float* cnb = out + 16973824;   // c_n region [6,64,512]

    dim3 blk(256);
    dim3 gGate(32, 128);   // N=4096, M=16384
    dim3 gProj(8, 128);    // N=1024

    // ---- Layer 0 ----
    gemm_t<0><<<gGate, blk>>>(x, M_TOT, 512, 4096, fWih0, bWih0, 2048,
                              fbi, bbi, gates, nullptr, nullptr);
    recur_k<<<128, blk>>>(fWhh, bWhh, finit, binit, masks, gates, bufA, hnb, cnb);

    // ---- Layer 1 ----
    gemm_t<0><<<gGate, blk>>>(bufA, M_TOT, 1024, 4096, fWihR, bWihR, 2048,
                              fbi + 2048, bbi + 2048, gates, nullptr, nullptr);
    recur_k<<<128, blk>>>(fWhh + 1048576, bWhh + 1048576, finit + 1024, binit + 1024,
                          masks, gates, bufB, hnb + 65536, cnb + 65536);
    // highway 1: bufA = g*bufB + (1-g)*bufA
    gemm_t<1><<<gProj, blk>>>(bufB, M_TOT, 1024, 1024, projW, projW, 1024,
                              projb, projb, bufA, bufB, bufA);

    // ---- Layer 2 ----
    gemm_t<0><<<gGate, blk>>>(bufA, M_TOT, 1024, 4096, fWihR + 2097152, bWihR + 2097152, 2048,
                              fbi + 4096, bbi + 4096, gates, nullptr, nullptr);
    recur_k<<<128, blk>>>(fWhh + 2097152, bWhh + 2097152, finit + 2048, binit + 2048,
                          masks, gates, bufB, hnb + 131072, cnb + 131072);
    // highway 2: d_out = g*bufB + (1-g)*bufA
    gemm_t<1><<<gProj, blk>>>(bufB, M_TOT, 1024, 1024, projW + 1048576, projW + 1048576, 1024,
                              projb + 1024, projb + 1024, out, bufB, bufA);
}